// round 8
// baseline (speedup 1.0000x reference)
#include <cuda_runtime.h>
#include <cuda_bf16.h>
#include <math.h>
#include <stdint.h>

// Sigma_out[b][i][l] = p_i * p_l * ( S[i][l] - q[i] - r[l] + s )
//   p = softmax(mu[b]) ; q = S p ; r = p^T S ; s = p^T S p
//
// Both DRAM streams via bulk copy engines:
//   read : double-buffered 64KB cp.async.bulk  global->shared (mbarrier)
//   write: in-place transform in smem, then 64KB cp.async.bulk shared->global
// The SM pipeline only ever touches shared memory; DRAM sees 64KB
// sequential bursts in each direction (minimal R/W turnaround).

#define C 128
#define THREADS 256
#define TILE_ELEMS (C * C)
#define TILE_BYTES (TILE_ELEMS * 4)
#define NUM_SMS 148

#define OFF_BUF0  0
#define OFF_BUF1  TILE_ELEMS
#define OFF_PSH   (2 * TILE_ELEMS)
#define OFF_QSH   (OFF_PSH + C)
#define OFF_PQ    (OFF_QSH + C)
#define OFF_RSUM  (OFF_PQ + C)
#define OFF_RPART (OFF_RSUM + C)
#define OFF_RED   (OFF_RPART + 8 * C)
#define OFF_MBAR  (OFF_RED + 16)
#define SMEM_FLOATS (OFF_MBAR + 4)

__device__ __forceinline__ uint32_t smem_u32(const void* p) {
    uint32_t a;
    asm("{ .reg .u64 tmp; cvta.to.shared.u64 tmp, %1; cvt.u32.u64 %0, tmp; }"
        : "=r"(a) : "l"(p));
    return a;
}
__device__ __forceinline__ void mbar_init(uint32_t mbar, uint32_t cnt) {
    asm volatile("mbarrier.init.shared.b64 [%0], %1;" :: "r"(mbar), "r"(cnt) : "memory");
}
__device__ __forceinline__ void mbar_expect_tx(uint32_t mbar, uint32_t bytes) {
    asm volatile("mbarrier.arrive.expect_tx.shared.b64 _, [%0], %1;"
                 :: "r"(mbar), "r"(bytes) : "memory");
}
__device__ __forceinline__ void bulk_load(uint32_t dst, const void* src,
                                          uint32_t bytes, uint32_t mbar) {
    asm volatile(
        "cp.async.bulk.shared::cluster.global.mbarrier::complete_tx::bytes "
        "[%0], [%1], %2, [%3];"
        :: "r"(dst), "l"(src), "r"(bytes), "r"(mbar) : "memory");
}
__device__ __forceinline__ void bulk_store(void* dst, uint32_t src, uint32_t bytes) {
    asm volatile(
        "cp.async.bulk.global.shared::cta.bulk_group [%0], [%1], %2;"
        :: "l"(dst), "r"(src), "r"(bytes) : "memory");
}
__device__ __forceinline__ void bulk_commit() {
    asm volatile("cp.async.bulk.commit_group;" ::: "memory");
}
__device__ __forceinline__ void bulk_wait_all() {
    asm volatile("cp.async.bulk.wait_group.read 0;" ::: "memory");
}
__device__ __forceinline__ void fence_async_shared() {
    asm volatile("fence.proxy.async.shared::cta;" ::: "memory");
}
__device__ __forceinline__ void mbar_wait(uint32_t mbar, uint32_t parity) {
    uint32_t done;
    asm volatile(
        "{\n\t.reg .pred p;\n\t"
        "mbarrier.try_wait.parity.acquire.cta.shared::cta.b64 p, [%1], %2;\n\t"
        "selp.b32 %0, 1, 0, p;\n\t}"
        : "=r"(done) : "r"(mbar), "r"(parity) : "memory");
    if (!done) {
        asm volatile(
            "{\n\t.reg .pred P1;\n\t"
            "WL_%=:\n\t"
            "mbarrier.try_wait.parity.acquire.cta.shared::cta.b64 P1, [%0], %1, 0x989680;\n\t"
            "@P1 bra.uni WD_%=;\n\t"
            "bra.uni WL_%=;\n\t"
            "WD_%=:\n\t}"
            :: "r"(mbar), "r"(parity) : "memory");
    }
}

__global__ __launch_bounds__(THREADS, 1) void softmax_sigma_tma2(
    const float* __restrict__ mu,
    const float* __restrict__ Sigma,
    float* __restrict__ mu_out,
    float* __restrict__ sig_out,
    int B)
{
    extern __shared__ float sm[];
    float* psh   = sm + OFF_PSH;
    float* qsh   = sm + OFF_QSH;
    float* pq    = sm + OFF_PQ;
    float* rsum  = sm + OFF_RSUM;
    float* rpart = sm + OFF_RPART;
    float* red   = sm + OFF_RED;

    const int t    = threadIdx.x;
    const int w    = t >> 5;
    const int lane = t & 31;
    const int k    = t & (C - 1);
    const int c2   = t >> 7;

    const uint32_t buf_addr[2] = { smem_u32(sm + OFF_BUF0), smem_u32(sm + OFF_BUF1) };
    const uint32_t mbar[2]     = { smem_u32(sm + OFF_MBAR), smem_u32(sm + OFF_MBAR) + 8 };

    if (t == 0) { mbar_init(mbar[0], 1); mbar_init(mbar[1], 1); }
    __syncthreads();

    const int stride = gridDim.x;
    int b   = blockIdx.x;
    int cur = 0;
    uint32_t parity[2] = { 0u, 0u };

    if (t == 0 && b < B) {
        mbar_expect_tx(mbar[0], TILE_BYTES);
        bulk_load(buf_addr[0], Sigma + (size_t)b * TILE_ELEMS, TILE_BYTES, mbar[0]);
    }
    float xmu = (t < C && b < B) ? mu[b * C + t] : -INFINITY;

    while (b < B) {
        const int bn  = b + stride;
        const int oth = cur ^ 1;

        // free `oth` (its store, issued 1 iter ago, must drain) then load bn
        if (t == 0 && bn < B) {
            bulk_wait_all();
            mbar_expect_tx(mbar[oth], TILE_BYTES);
            bulk_load(buf_addr[oth], Sigma + (size_t)bn * TILE_ELEMS, TILE_BYTES, mbar[oth]);
        }
        float xmun = (t < C && bn < B) ? mu[bn * C + t] : -INFINITY;

        // ---- softmax over mu[b] (overlaps in-flight loads)
        float v = xmu;
        #pragma unroll
        for (int o = 16; o > 0; o >>= 1)
            v = fmaxf(v, __shfl_xor_sync(0xffffffffu, v, o));
        if (t < C && lane == 0) red[w] = v;
        __syncthreads();
        float m = fmaxf(fmaxf(red[0], red[1]), fmaxf(red[2], red[3]));
        float e = (t < C) ? expf(xmu - m) : 0.0f;
        v = e;
        #pragma unroll
        for (int o = 16; o > 0; o >>= 1)
            v += __shfl_xor_sync(0xffffffffu, v, o);
        if (t < C && lane == 0) red[8 + w] = v;
        __syncthreads();
        float denom = red[8] + red[9] + red[10] + red[11];
        if (t < C) {
            float pt = e / denom;
            psh[t] = pt;
            mu_out[b * C + t] = pt;
        }
        __syncthreads();

        // ---- wait for this batch's tile
        mbar_wait(mbar[cur], parity[cur]);
        parity[cur] ^= 1u;
        float* bp = sm + (cur ? OFF_BUF1 : OFF_BUF0);

        // ---- fused q/r pass (warp w -> rows i = w + 8*jj)
        {
            const float pk0 = psh[lane];
            const float pk1 = psh[lane + 32];
            const float pk2 = psh[lane + 64];
            const float pk3 = psh[lane + 96];
            float r0 = 0.f, r1 = 0.f, r2 = 0.f, r3 = 0.f;
            #pragma unroll
            for (int jj = 0; jj < 16; ++jj) {
                const int i = w + 8 * jj;
                const float* row = bp + i * C;
                float v0 = row[lane], v1 = row[lane + 32];
                float v2 = row[lane + 64], v3 = row[lane + 96];
                float pi = psh[i];
                r0 = fmaf(v0, pi, r0); r1 = fmaf(v1, pi, r1);
                r2 = fmaf(v2, pi, r2); r3 = fmaf(v3, pi, r3);
                float qs = fmaf(v0, pk0, fmaf(v1, pk1, fmaf(v2, pk2, v3 * pk3)));
                #pragma unroll
                for (int o = 16; o > 0; o >>= 1)
                    qs += __shfl_xor_sync(0xffffffffu, qs, o);
                if (lane == jj) qsh[i] = qs;
            }
            rpart[w * C + lane]      = r0;
            rpart[w * C + lane + 32] = r1;
            rpart[w * C + lane + 64] = r2;
            rpart[w * C + lane + 96] = r3;
        }
        __syncthreads();

        // ---- r reduction, s, pq
        float qi = 0.f;
        if (t < C) {
            float rk = 0.f;
            #pragma unroll
            for (int ww = 0; ww < 8; ++ww) rk += rpart[ww * C + t];
            rsum[t] = rk;
            qi = qsh[t];
        }
        float sv = (t < C) ? qi * psh[t] : 0.0f;
        #pragma unroll
        for (int o = 16; o > 0; o >>= 1)
            sv += __shfl_xor_sync(0xffffffffu, sv, o);
        if (t < C && lane == 0) red[w] = sv;
        __syncthreads();
        const float s = red[0] + red[1] + red[2] + red[3];
        if (t < C) pq[t] = psh[t] * (qi - s);
        __syncthreads();

        // ---- in-place transform: bp[i][k] <- p_k*(p_i*(bp[i][k]-r_k)-pq[i])
        {
            const float pk  = psh[k];
            const float rkv = rsum[k];
            int i = c2;
            #pragma unroll
            for (int j = 0; j < 64; ++j) {
                float* cell = bp + i * C + k;
                *cell = pk * (psh[i] * (*cell - rkv) - pq[i]);
                i += 2;
            }
        }
        fence_async_shared();
        __syncthreads();

        // ---- bulk store this tile (drained before buffer reuse next iter)
        if (t == 0) {
            bulk_store(sig_out + (size_t)b * TILE_ELEMS, buf_addr[cur], TILE_BYTES);
            bulk_commit();
        }

        b = bn; xmu = xmun; cur = oth;
    }
    if (t == 0) bulk_wait_all();   // all stores landed before exit
}

// ---------------- fallback: proven round-3 scalar kernel ------------------
__global__ __launch_bounds__(THREADS) void softmax_sigma_fallback(
    const float* __restrict__ mu, const float* __restrict__ Sigma,
    float* __restrict__ mu_out, float* __restrict__ sig_out)
{
    const int b = blockIdx.x;
    const int t = threadIdx.x;
    extern __shared__ float sm[];
    float* Ssm = sm; float* p = sm + C * C; float* qv = p + C;
    float* rv = qv + C; float* red = rv + C;
    const float* Sb = Sigma + (size_t)b * (C * C);
    float* Ob = sig_out + (size_t)b * (C * C);

    float x = (t < C) ? mu[b * C + t] : -INFINITY;
    float v = x;
    #pragma unroll
    for (int o = 16; o > 0; o >>= 1) v = fmaxf(v, __shfl_xor_sync(~0u, v, o));
    if (t < C && (t & 31) == 0) red[t >> 5] = v;
    #pragma unroll
    for (int j = 0; j < 64; ++j) {
        int el = t + THREADS * j; int i = el >> 7; int kk = el & (C - 1);
        Ssm[i * C + (kk ^ (i & 31))] = Sb[el];
    }
    __syncthreads();
    float m = fmaxf(fmaxf(red[0], red[1]), fmaxf(red[2], red[3]));
    float e = (t < C) ? expf(x - m) : 0.0f;
    v = e;
    #pragma unroll
    for (int o = 16; o > 0; o >>= 1) v += __shfl_xor_sync(~0u, v, o);
    if (t < C && (t & 31) == 0) red[8 + (t >> 5)] = v;
    __syncthreads();
    float denom = red[8] + red[9] + red[10] + red[11];
    if (t < C) { float pt = e / denom; p[t] = pt; mu_out[b * C + t] = pt; }
    __syncthreads();
    if (t < C) {
        const int i = t, sw = i & 31; const float* row = Ssm + i * C;
        float acc = 0.f;
        #pragma unroll 8
        for (int kk = 0; kk < C; ++kk) acc = fmaf(row[kk ^ sw], p[kk], acc);
        qv[i] = acc;
    } else {
        const int kk = t - C; float acc = 0.f;
        #pragma unroll 8
        for (int i2 = 0; i2 < C; ++i2) acc = fmaf(Ssm[i2 * C + (kk ^ (i2 & 31))], p[i2], acc);
        rv[kk] = acc;
    }
    __syncthreads();
    float sv = (t < C) ? qv[t] * p[t] : 0.f;
    #pragma unroll
    for (int o = 16; o > 0; o >>= 1) sv += __shfl_xor_sync(~0u, sv, o);
    if (t < C && (t & 31) == 0) red[t >> 5] = sv;
    __syncthreads();
    const float s = red[0] + red[1] + red[2] + red[3];
    #pragma unroll
    for (int j = 0; j < 64; ++j) {
        int el = t + THREADS * j; int i = el >> 7; int kk = el & (C - 1);
        float val = Ssm[i * C + (kk ^ (i & 31))];
        Ob[el] = p[i] * p[kk] * (val - rv[kk] - (qv[i] - s));
    }
}

extern "C" void kernel_launch(void* const* d_in, const int* in_sizes, int n_in,
                              void* d_out, int out_size)
{
    const float* in0 = (const float*)d_in[0];
    const float* in1 = (const float*)d_in[1];
    const float* mu; const float* Sigma; int B;
    if (in_sizes[0] <= in_sizes[1]) { mu = in0; Sigma = in1; B = in_sizes[0] / C; }
    else                            { mu = in1; Sigma = in0; B = in_sizes[1] / C; }

    float* mu_out  = (float*)d_out;
    float* sig_out = (float*)d_out + (size_t)B * C;

    if ((((uintptr_t)Sigma   & 15) == 0) &&
        (((uintptr_t)sig_out & 15) == 0)) {
        const int smem = SMEM_FLOATS * sizeof(float);
        cudaFuncSetAttribute(softmax_sigma_tma2,
                             cudaFuncAttributeMaxDynamicSharedMemorySize, smem);
        int grid = NUM_SMS; if (grid > B) grid = B;
        softmax_sigma_tma2<<<grid, THREADS, smem>>>(mu, Sigma, mu_out, sig_out, B);
    } else {
        const int smem = (C * C + 3 * C + 16) * sizeof(float);
        cudaFuncSetAttribute(softmax_sigma_fallback,
                             cudaFuncAttributeMaxDynamicSharedMemorySize, smem);
        softmax_sigma_fallback<<<B, THREADS, smem>>>(mu, Sigma, mu_out, sig_out);
    }
}

// round 9
// speedup vs baseline: 1.2065x; 1.2065x over previous
#include <cuda_runtime.h>
#include <cuda_bf16.h>
#include <math.h>
#include <stdint.h>

// Sigma_out[b][i][l] = p_i * p_l * ( S[i][l] - q[i] - r[l] + s )
//   p = softmax(mu[b]) ; q = S p ; r = p^T S ; s = p^T S p
//
// Triple-buffered bulk-copy pipeline, 1 CTA/SM, 512 threads:
//   read : cp.async.bulk 64KB tiles, issued one batch ahead (mbarrier)
//   write: in-place transform in smem, cp.async.bulk smem->global;
//          drain guarded by wait_group.read 1 a full iteration later.
// DRAM sees 64KB sequential bursts both ways; SM only touches smem.

#define C 128
#define THREADS 512
#define TILE_ELEMS (C * C)
#define TILE_BYTES (TILE_ELEMS * 4)
#define NUM_SMS 148
#define NBUF 3

#define OFF_PSH   (NBUF * TILE_ELEMS)
#define OFF_QSH   (OFF_PSH + C)
#define OFF_PQ    (OFF_QSH + C)
#define OFF_RSUM  (OFF_PQ + C)
#define OFF_RPART (OFF_RSUM + C)          // 16*128
#define OFF_RED   (OFF_RPART + 16 * C)    // 16
#define OFF_MBAR  (OFF_RED + 16)          // 3 mbarriers = 6 floats
#define SMEM_FLOATS (OFF_MBAR + 6)

__device__ __forceinline__ uint32_t smem_u32(const void* p) {
    uint32_t a;
    asm("{ .reg .u64 tmp; cvta.to.shared.u64 tmp, %1; cvt.u32.u64 %0, tmp; }"
        : "=r"(a) : "l"(p));
    return a;
}
__device__ __forceinline__ void mbar_init(uint32_t mbar, uint32_t cnt) {
    asm volatile("mbarrier.init.shared.b64 [%0], %1;" :: "r"(mbar), "r"(cnt) : "memory");
}
__device__ __forceinline__ void mbar_expect_tx(uint32_t mbar, uint32_t bytes) {
    asm volatile("mbarrier.arrive.expect_tx.shared.b64 _, [%0], %1;"
                 :: "r"(mbar), "r"(bytes) : "memory");
}
__device__ __forceinline__ void bulk_load(uint32_t dst, const void* src,
                                          uint32_t bytes, uint32_t mbar) {
    asm volatile(
        "cp.async.bulk.shared::cluster.global.mbarrier::complete_tx::bytes "
        "[%0], [%1], %2, [%3];"
        :: "r"(dst), "l"(src), "r"(bytes), "r"(mbar) : "memory");
}
__device__ __forceinline__ void bulk_store(void* dst, uint32_t src, uint32_t bytes) {
    asm volatile(
        "cp.async.bulk.global.shared::cta.bulk_group [%0], [%1], %2;"
        :: "l"(dst), "r"(src), "r"(bytes) : "memory");
}
__device__ __forceinline__ void bulk_commit() {
    asm volatile("cp.async.bulk.commit_group;" ::: "memory");
}
__device__ __forceinline__ void bulk_wait_le1() {
    asm volatile("cp.async.bulk.wait_group.read 1;" ::: "memory");
}
__device__ __forceinline__ void bulk_wait_all() {
    asm volatile("cp.async.bulk.wait_group.read 0;" ::: "memory");
}
__device__ __forceinline__ void fence_async_shared() {
    asm volatile("fence.proxy.async.shared::cta;" ::: "memory");
}
__device__ __forceinline__ void mbar_wait(uint32_t mbar, uint32_t parity) {
    uint32_t done;
    asm volatile(
        "{\n\t.reg .pred p;\n\t"
        "mbarrier.try_wait.parity.acquire.cta.shared::cta.b64 p, [%1], %2;\n\t"
        "selp.b32 %0, 1, 0, p;\n\t}"
        : "=r"(done) : "r"(mbar), "r"(parity) : "memory");
    if (!done) {
        asm volatile(
            "{\n\t.reg .pred P1;\n\t"
            "WL_%=:\n\t"
            "mbarrier.try_wait.parity.acquire.cta.shared::cta.b64 P1, [%0], %1, 0x989680;\n\t"
            "@P1 bra.uni WD_%=;\n\t"
            "bra.uni WL_%=;\n\t"
            "WD_%=:\n\t}"
            :: "r"(mbar), "r"(parity) : "memory");
    }
}

__global__ __launch_bounds__(THREADS, 1) void softmax_sigma_tma3(
    const float* __restrict__ mu,
    const float* __restrict__ Sigma,
    float* __restrict__ mu_out,
    float* __restrict__ sig_out,
    int B)
{
    extern __shared__ float sm[];
    float* psh   = sm + OFF_PSH;
    float* qsh   = sm + OFF_QSH;
    float* pq    = sm + OFF_PQ;
    float* rsum  = sm + OFF_RSUM;
    float* rpart = sm + OFF_RPART;
    float* red   = sm + OFF_RED;

    const int t    = threadIdx.x;
    const int w    = t >> 5;           // 0..15
    const int lane = t & 31;
    const int k    = t & (C - 1);
    const int c4   = t >> 7;           // 0..3

    uint32_t buf_addr[NBUF], mbar[NBUF];
    #pragma unroll
    for (int i = 0; i < NBUF; ++i) {
        buf_addr[i] = smem_u32(sm + i * TILE_ELEMS);
        mbar[i]     = smem_u32(sm + OFF_MBAR) + 8u * i;
    }
    if (t == 0) {
        #pragma unroll
        for (int i = 0; i < NBUF; ++i) mbar_init(mbar[i], 1);
    }
    __syncthreads();

    const int stride = gridDim.x;
    int b   = blockIdx.x;
    int buf = 0;
    uint32_t par[NBUF] = { 0u, 0u, 0u };

    if (t == 0 && b < B) {
        mbar_expect_tx(mbar[0], TILE_BYTES);
        bulk_load(buf_addr[0], Sigma + (size_t)b * TILE_ELEMS, TILE_BYTES, mbar[0]);
    }
    float xmu = (t < C && b < B) ? mu[b * C + t] : -INFINITY;

    while (b < B) {
        const int bn = b + stride;
        const int nb = (buf + 1 == NBUF) ? 0 : buf + 1;

        // issue next tile load; its buffer's store (iter n-2) has had a full
        // iteration to drain -> wait_group.read 1 is (nearly) free.
        if (t == 0 && bn < B) {
            bulk_wait_le1();
            mbar_expect_tx(mbar[nb], TILE_BYTES);
            bulk_load(buf_addr[nb], Sigma + (size_t)bn * TILE_ELEMS, TILE_BYTES, mbar[nb]);
        }
        float xmun = (t < C && bn < B) ? mu[bn * C + t] : -INFINITY;

        // ---- softmax over mu[b] (overlaps in-flight bulk traffic)
        float v = xmu;
        #pragma unroll
        for (int o = 16; o > 0; o >>= 1)
            v = fmaxf(v, __shfl_xor_sync(0xffffffffu, v, o));
        if (t < C && lane == 0) red[w] = v;
        __syncthreads();
        float m = fmaxf(fmaxf(red[0], red[1]), fmaxf(red[2], red[3]));
        float e = (t < C) ? expf(xmu - m) : 0.0f;
        v = e;
        #pragma unroll
        for (int o = 16; o > 0; o >>= 1)
            v += __shfl_xor_sync(0xffffffffu, v, o);
        if (t < C && lane == 0) red[8 + w] = v;
        __syncthreads();
        float denom = red[8] + red[9] + red[10] + red[11];
        if (t < C) {
            float pt = e / denom;
            psh[t] = pt;
            mu_out[b * C + t] = pt;
        }
        __syncthreads();

        // ---- wait for this batch's tile
        mbar_wait(mbar[buf], par[buf]);
        par[buf] ^= 1u;
        float* bp = sm + buf * TILE_ELEMS;

        // ---- fused q/r pass: warp w handles rows i = w + 16*jj (8 rows)
        {
            const float pk0 = psh[lane];
            const float pk1 = psh[lane + 32];
            const float pk2 = psh[lane + 64];
            const float pk3 = psh[lane + 96];
            float r0 = 0.f, r1 = 0.f, r2 = 0.f, r3 = 0.f;
            #pragma unroll
            for (int jj = 0; jj < 8; ++jj) {
                const int i = w + 16 * jj;
                const float* row = bp + i * C;
                float v0 = row[lane], v1 = row[lane + 32];
                float v2 = row[lane + 64], v3 = row[lane + 96];
                float pi = psh[i];
                r0 = fmaf(v0, pi, r0); r1 = fmaf(v1, pi, r1);
                r2 = fmaf(v2, pi, r2); r3 = fmaf(v3, pi, r3);
                float qs = fmaf(v0, pk0, fmaf(v1, pk1, fmaf(v2, pk2, v3 * pk3)));
                #pragma unroll
                for (int o = 16; o > 0; o >>= 1)
                    qs += __shfl_xor_sync(0xffffffffu, qs, o);
                if (lane == jj) qsh[i] = qs;
            }
            rpart[w * C + lane]      = r0;
            rpart[w * C + lane + 32] = r1;
            rpart[w * C + lane + 64] = r2;
            rpart[w * C + lane + 96] = r3;
        }
        __syncthreads();

        // ---- r reduction, s, pq
        float qi = 0.f;
        if (t < C) {
            float rk = 0.f;
            #pragma unroll
            for (int ww = 0; ww < 16; ++ww) rk += rpart[ww * C + t];
            rsum[t] = rk;
            qi = qsh[t];
        }
        float sv = (t < C) ? qi * psh[t] : 0.0f;
        #pragma unroll
        for (int o = 16; o > 0; o >>= 1)
            sv += __shfl_xor_sync(0xffffffffu, sv, o);
        if (t < C && lane == 0) red[w] = sv;
        __syncthreads();
        const float s = red[0] + red[1] + red[2] + red[3];
        if (t < C) pq[t] = psh[t] * (qi - s);
        __syncthreads();

        // ---- in-place: bp[i][k] <- p_k*(p_i*(bp[i][k]-r_k)-pq[i])
        {
            const float pk  = psh[k];
            const float rkv = rsum[k];
            int i = c4;
            #pragma unroll
            for (int j = 0; j < 32; ++j) {
                float* cell = bp + i * C + k;
                *cell = pk * (psh[i] * (*cell - rkv) - pq[i]);
                i += 4;
            }
        }
        fence_async_shared();
        __syncthreads();

        if (t == 0) {
            bulk_store(sig_out + (size_t)b * TILE_ELEMS, buf_addr[buf], TILE_BYTES);
            bulk_commit();
        }

        b = bn; xmu = xmun; buf = nb;
    }
    if (t == 0) bulk_wait_all();
}

// ---------------- fallback: proven round-3 scalar kernel ------------------
#define FTHREADS 256
__global__ __launch_bounds__(FTHREADS) void softmax_sigma_fallback(
    const float* __restrict__ mu, const float* __restrict__ Sigma,
    float* __restrict__ mu_out, float* __restrict__ sig_out)
{
    const int b = blockIdx.x;
    const int t = threadIdx.x;
    extern __shared__ float sm[];
    float* Ssm = sm; float* p = sm + C * C; float* qv = p + C;
    float* rv = qv + C; float* red = rv + C;
    const float* Sb = Sigma + (size_t)b * (C * C);
    float* Ob = sig_out + (size_t)b * (C * C);

    float x = (t < C) ? mu[b * C + t] : -INFINITY;
    float v = x;
    #pragma unroll
    for (int o = 16; o > 0; o >>= 1) v = fmaxf(v, __shfl_xor_sync(~0u, v, o));
    if (t < C && (t & 31) == 0) red[t >> 5] = v;
    #pragma unroll
    for (int j = 0; j < 64; ++j) {
        int el = t + FTHREADS * j; int i = el >> 7; int kk = el & (C - 1);
        Ssm[i * C + (kk ^ (i & 31))] = Sb[el];
    }
    __syncthreads();
    float m = fmaxf(fmaxf(red[0], red[1]), fmaxf(red[2], red[3]));
    float e = (t < C) ? expf(x - m) : 0.0f;
    v = e;
    #pragma unroll
    for (int o = 16; o > 0; o >>= 1) v += __shfl_xor_sync(~0u, v, o);
    if (t < C && (t & 31) == 0) red[8 + (t >> 5)] = v;
    __syncthreads();
    float denom = red[8] + red[9] + red[10] + red[11];
    if (t < C) { float pt = e / denom; p[t] = pt; mu_out[b * C + t] = pt; }
    __syncthreads();
    if (t < C) {
        const int i = t, sw = i & 31; const float* row = Ssm + i * C;
        float acc = 0.f;
        #pragma unroll 8
        for (int kk = 0; kk < C; ++kk) acc = fmaf(row[kk ^ sw], p[kk], acc);
        qv[i] = acc;
    } else {
        const int kk = t - C; float acc = 0.f;
        #pragma unroll 8
        for (int i2 = 0; i2 < C; ++i2) acc = fmaf(Ssm[i2 * C + (kk ^ (i2 & 31))], p[i2], acc);
        rv[kk] = acc;
    }
    __syncthreads();
    float sv = (t < C) ? qv[t] * p[t] : 0.f;
    #pragma unroll
    for (int o = 16; o > 0; o >>= 1) sv += __shfl_xor_sync(~0u, sv, o);
    if (t < C && (t & 31) == 0) red[t >> 5] = sv;
    __syncthreads();
    const float s = red[0] + red[1] + red[2] + red[3];
    #pragma unroll
    for (int j = 0; j < 64; ++j) {
        int el = t + FTHREADS * j; int i = el >> 7; int kk = el & (C - 1);
        float val = Ssm[i * C + (kk ^ (i & 31))];
        Ob[el] = p[i] * p[kk] * (val - rv[kk] - (qv[i] - s));
    }
}

extern "C" void kernel_launch(void* const* d_in, const int* in_sizes, int n_in,
                              void* d_out, int out_size)
{
    const float* in0 = (const float*)d_in[0];
    const float* in1 = (const float*)d_in[1];
    const float* mu; const float* Sigma; int B;
    if (in_sizes[0] <= in_sizes[1]) { mu = in0; Sigma = in1; B = in_sizes[0] / C; }
    else                            { mu = in1; Sigma = in0; B = in_sizes[1] / C; }

    float* mu_out  = (float*)d_out;
    float* sig_out = (float*)d_out + (size_t)B * C;

    if ((((uintptr_t)Sigma   & 15) == 0) &&
        (((uintptr_t)sig_out & 15) == 0)) {
        const int smem = SMEM_FLOATS * sizeof(float);   // ~203 KB
        cudaFuncSetAttribute(softmax_sigma_tma3,
                             cudaFuncAttributeMaxDynamicSharedMemorySize, smem);
        int grid = NUM_SMS; if (grid > B) grid = B;
        softmax_sigma_tma3<<<grid, THREADS, smem>>>(mu, Sigma, mu_out, sig_out, B);
    } else {
        const int smem = (C * C + 3 * C + 16) * sizeof(float);
        cudaFuncSetAttribute(softmax_sigma_fallback,
                             cudaFuncAttributeMaxDynamicSharedMemorySize, smem);
        softmax_sigma_fallback<<<B, FTHREADS, smem>>>(mu, Sigma, mu_out, sig_out);
    }
}

// round 10
// speedup vs baseline: 1.4132x; 1.1713x over previous
#include <cuda_runtime.h>
#include <cuda_bf16.h>
#include <math.h>
#include <stdint.h>

// Sigma_out[b][i][l] = p_i * p_l * ( S[i][l] - q[i] - r[l] + s )
//   p = softmax(mu[b]) ; q = S p ; r = p^T S ; s = p^T S p
//
// Best-of-all-rounds combination (empirical wall ~5.1 TB/s for this R/W mix):
//   - one CTA per batch, grid = B, 256 threads, 2 CTAs/SM (full reg budget)
//   - PF=24 Sigma values prefetched into registers before the softmax
//     reductions, so reads are in flight through the serial section
//   - r (= p^T S) fused into the staging pass (register accumulation,
//     column k fixed per thread) -> no separate r smem pass
//   - q pass split across all 256 threads (half-row each)
//   - Sigma in smem with per-row XOR swizzle: row i, col k at
//     [i*C + (k ^ (i&31))]; staging STS, q LDS and output LDS all
//     bank-conflict free
//   - all global accesses scalar 32-bit (vector accesses faulted on this
//     harness; scalar LDG/STG is not the bottleneck at the DRAM wall)

#define C 128
#define THREADS 256
#define EPT 64          // Sigma elements per thread
#define PF 24           // register prefetch depth

__global__ __launch_bounds__(THREADS, 2) void softmax_sigma_kernel(
    const float* __restrict__ mu,       // [B, C]
    const float* __restrict__ Sigma,    // [B, C, C]
    float* __restrict__ mu_out,         // [B, C]
    float* __restrict__ sig_out)        // [B, C, C]
{
    const int b = blockIdx.x;
    const int t = threadIdx.x;
    const int k = t & (C - 1);          // fixed column for this thread
    const int c = t >> 7;               // 0 or 1

    extern __shared__ float sm[];
    float* Ssm   = sm;                  // 16384 swizzled Sigma
    float* psh   = sm + C * C;          // 128  softmax p
    float* pq    = psh + C;             // 128  p_i*(q_i - s)
    float* rtmp  = pq + C;              // 256  r partials (2 per k)
    float* qpart = rtmp + 2 * C;        // 256  q partials (2 per i)
    float* red   = qpart + 2 * C;       // 16   reduction scratch

    const float* g = Sigma + (size_t)b * (C * C) + t;

    // ---- deep prefetch: 24 coalesced LDGs in flight before the serial part
    float pf[PF];
    #pragma unroll
    for (int j = 0; j < PF; ++j) pf[j] = g[THREADS * j];

    // ---- softmax over mu[b] (threads 0..127 own one class)
    float x = (t < C) ? mu[b * C + t] : -INFINITY;
    float v = x;
    #pragma unroll
    for (int o = 16; o > 0; o >>= 1)
        v = fmaxf(v, __shfl_xor_sync(0xffffffffu, v, o));
    if (t < C && (t & 31) == 0) red[t >> 5] = v;
    __syncthreads();
    float m = fmaxf(fmaxf(red[0], red[1]), fmaxf(red[2], red[3]));
    float e = (t < C) ? expf(x - m) : 0.0f;
    v = e;
    #pragma unroll
    for (int o = 16; o > 0; o >>= 1)
        v += __shfl_xor_sync(0xffffffffu, v, o);
    if (t < C && (t & 31) == 0) red[8 + (t >> 5)] = v;
    __syncthreads();
    float denom = red[8] + red[9] + red[10] + red[11];
    if (t < C) {
        float pt = e / denom;
        psh[t] = pt;
        mu_out[b * C + t] = pt;
    }
    __syncthreads();

    // ---- staging + fused r accumulation (k fixed; rows i = c, c+2, ...)
    {
        float racc = 0.0f;
        int i = c;
        #pragma unroll
        for (int j = 0; j < EPT; ++j) {
            float val = (j < PF) ? pf[j] : g[THREADS * j];
            Ssm[i * C + (k ^ (i & 31))] = val;
            racc = fmaf(val, psh[i], racc);   // psh[i]: warp-uniform broadcast
            i += 2;
        }
        rtmp[t] = racc;   // r[k] = rtmp[k] + rtmp[k+128]
    }
    __syncthreads();

    // ---- q pass: thread t -> row i = t&127, column half [64c, 64c+64)
    {
        const int i  = k;                 // row index
        const int sw = i & 31;
        const float* row = Ssm + i * C;
        float acc = 0.0f;
        #pragma unroll 8
        for (int kk = 0; kk < 64; ++kk) {
            int kc = 64 * c + kk;         // warp-uniform
            acc = fmaf(row[kc ^ sw], psh[kc], acc);
        }
        qpart[t] = acc;   // q[i] = qpart[i] + qpart[i+128]
    }
    __syncthreads();

    // ---- s = p . q ; pq[i] = p_i*(q_i - s)
    float qi = (t < C) ? (qpart[t] + qpart[t + C]) : 0.0f;
    float sv = (t < C) ? psh[t] * qi : 0.0f;
    #pragma unroll
    for (int o = 16; o > 0; o >>= 1)
        sv += __shfl_xor_sync(0xffffffffu, sv, o);
    if (t < C && (t & 31) == 0) red[t >> 5] = sv;
    __syncthreads();
    const float s = red[0] + red[1] + red[2] + red[3];
    if (t < C) pq[t] = psh[t] * (qi - s);
    __syncthreads();

    // ---- output: out[i][k] = p_k * ( p_i*(S[i][k] - r_k) - pq[i] )
    {
        const float pk = psh[k];
        const float rk = rtmp[k] + rtmp[k + C];
        float* o = sig_out + (size_t)b * (C * C) + t;
        int i = c;
        #pragma unroll
        for (int j = 0; j < EPT; ++j) {
            float val = Ssm[i * C + (k ^ (i & 31))];
            o[THREADS * j] = pk * (psh[i] * (val - rk) - pq[i]);
            i += 2;
        }
    }
}

extern "C" void kernel_launch(void* const* d_in, const int* in_sizes, int n_in,
                              void* d_out, int out_size)
{
    // Identify inputs by size: Sigma is C times larger than mu.
    const float* in0 = (const float*)d_in[0];
    const float* in1 = (const float*)d_in[1];
    const float* mu;
    const float* Sigma;
    int B;
    if (in_sizes[0] <= in_sizes[1]) {
        mu = in0; Sigma = in1; B = in_sizes[0] / C;
    } else {
        mu = in1; Sigma = in0; B = in_sizes[1] / C;
    }

    float* mu_out  = (float*)d_out;               // first B*C elements
    float* sig_out = (float*)d_out + (size_t)B * C;

    const int smem = (C * C + 2 * C + 2 * (2 * C) + 16) * sizeof(float);
    cudaFuncSetAttribute(softmax_sigma_kernel,
                         cudaFuncAttributeMaxDynamicSharedMemorySize, smem);
    softmax_sigma_kernel<<<B, THREADS, smem>>>(mu, Sigma, mu_out, sig_out);
}

// round 11
// speedup vs baseline: 1.4752x; 1.0439x over previous
#include <cuda_runtime.h>
#include <cuda_bf16.h>
#include <math.h>
#include <stdint.h>

// Sigma_out[b][i][l] = p_i * p_l * ( S[i][l] - q[i] - r[l] + s )
//   p = softmax(mu[b]) ; q = S p ; r = p^T S ; s = p^T S p
//
// r10 winner + l1tex reduction:
//   - one CTA per batch, 256 threads, 2 CTAs/SM (full register budget)
//   - PF=24 Sigma values prefetched AND retained in registers to the end
//     (output pass reads them instead of smem)
//   - r fused into staging (register accumulation, fixed column per thread)
//   - 16B-block swizzle: (i,k) stored at i*128 + 4*((k>>2)^(i&31)) + (k&3)
//       * staging STS scalar: banks 4*perm8 + (k&3) -> conflict-free
//       * q-pass: LDS.128 (16 float4 per thread) + float4 psh loads
//       * output LDS scalar: same conflict-free pattern
//   - global accesses stay scalar 32-bit (vector-global faults on this harness)

#define C 128
#define THREADS 256
#define EPT 64
#define PF 24

__global__ __launch_bounds__(THREADS, 2) void softmax_sigma_kernel(
    const float* __restrict__ mu,       // [B, C]
    const float* __restrict__ Sigma,    // [B, C, C]
    float* __restrict__ mu_out,         // [B, C]
    float* __restrict__ sig_out)        // [B, C, C]
{
    const int b  = blockIdx.x;
    const int t  = threadIdx.x;
    const int k  = t & (C - 1);         // fixed column for this thread
    const int c  = t >> 7;              // 0 or 1
    const int kb = k >> 2;              // fixed 16B block of column
    const int ko = k & 3;               // offset within block

    extern __shared__ __align__(16) float sm[];
    float* Ssm   = sm;                  // 16384, block-swizzled
    float* psh   = sm + C * C;          // 128
    float* pq    = psh + C;             // 128
    float* rtmp  = pq + C;              // 256
    float* qpart = rtmp + 2 * C;        // 256
    float* red   = qpart + 2 * C;       // 16

    const float* g = Sigma + (size_t)b * (C * C) + t;

    // ---- deep prefetch, retained in registers through the whole kernel
    float pfv[PF];
    #pragma unroll
    for (int j = 0; j < PF; ++j) pfv[j] = g[THREADS * j];

    // ---- softmax over mu[b]
    float x = (t < C) ? mu[b * C + t] : -INFINITY;
    float v = x;
    #pragma unroll
    for (int o = 16; o > 0; o >>= 1)
        v = fmaxf(v, __shfl_xor_sync(0xffffffffu, v, o));
    if (t < C && (t & 31) == 0) red[t >> 5] = v;
    __syncthreads();
    float m = fmaxf(fmaxf(red[0], red[1]), fmaxf(red[2], red[3]));
    float e = (t < C) ? expf(x - m) : 0.0f;
    v = e;
    #pragma unroll
    for (int o = 16; o > 0; o >>= 1)
        v += __shfl_xor_sync(0xffffffffu, v, o);
    if (t < C && (t & 31) == 0) red[8 + (t >> 5)] = v;
    __syncthreads();
    float denom = red[8] + red[9] + red[10] + red[11];
    if (t < C) {
        float pt = e / denom;
        psh[t] = pt;
        mu_out[b * C + t] = pt;
    }
    __syncthreads();

    // ---- staging + fused r accumulation (rows i = c, c+2, ...)
    {
        float racc = 0.0f;
        int i = c;
        #pragma unroll
        for (int j = 0; j < EPT; ++j) {
            float val = (j < PF) ? pfv[j] : g[THREADS * j];
            Ssm[i * C + (((kb ^ (i & 31)) << 2) | ko)] = val;
            racc = fmaf(val, psh[i], racc);
            i += 2;
        }
        rtmp[t] = racc;   // r[k] = rtmp[k] + rtmp[k+128]
    }
    __syncthreads();

    // ---- q pass, vectorized: thread t -> row iq = t&127, half c
    {
        const int iq = k;
        const int sw = iq & 31;
        const float4* row4 = reinterpret_cast<const float4*>(Ssm + iq * C);
        const float4* p4   = reinterpret_cast<const float4*>(psh);
        float acc = 0.0f;
        #pragma unroll
        for (int bb = 0; bb < 16; ++bb) {
            const int blk = 16 * c + bb;           // warp-uniform
            float4 vv = row4[blk ^ sw];
            float4 pp = p4[blk];
            acc = fmaf(vv.x, pp.x, acc);
            acc = fmaf(vv.y, pp.y, acc);
            acc = fmaf(vv.z, pp.z, acc);
            acc = fmaf(vv.w, pp.w, acc);
        }
        qpart[t] = acc;   // q[i] = qpart[i] + qpart[i+128]
    }
    __syncthreads();

    // ---- s = p . q ; pq[i] = p_i*(q_i - s)
    float qi = (t < C) ? (qpart[t] + qpart[t + C]) : 0.0f;
    float sv = (t < C) ? psh[t] * qi : 0.0f;
    #pragma unroll
    for (int o = 16; o > 0; o >>= 1)
        sv += __shfl_xor_sync(0xffffffffu, sv, o);
    if (t < C && (t & 31) == 0) red[t >> 5] = sv;
    __syncthreads();
    const float s = red[0] + red[1] + red[2] + red[3];
    if (t < C) pq[t] = psh[t] * (qi - s);
    __syncthreads();

    // ---- output: out[i][k] = p_k * ( p_i*(S[i][k] - r_k) - pq[i] )
    //      first PF values come straight from registers (no smem read)
    {
        const float pk = psh[k];
        const float rk = rtmp[k] + rtmp[k + C];
        float* o = sig_out + (size_t)b * (C * C) + t;
        int i = c;
        #pragma unroll
        for (int j = 0; j < EPT; ++j) {
            float val = (j < PF) ? pfv[j]
                                 : Ssm[i * C + (((kb ^ (i & 31)) << 2) | ko)];
            o[THREADS * j] = pk * (psh[i] * (val - rk) - pq[i]);
            i += 2;
        }
    }
}

extern "C" void kernel_launch(void* const* d_in, const int* in_sizes, int n_in,
                              void* d_out, int out_size)
{
    // Identify inputs by size: Sigma is C times larger than mu.
    const float* in0 = (const float*)d_in[0];
    const float* in1 = (const float*)d_in[1];
    const float* mu;
    const float* Sigma;
    int B;
    if (in_sizes[0] <= in_sizes[1]) {
        mu = in0; Sigma = in1; B = in_sizes[0] / C;
    } else {
        mu = in1; Sigma = in0; B = in_sizes[1] / C;
    }

    float* mu_out  = (float*)d_out;               // first B*C elements
    float* sig_out = (float*)d_out + (size_t)B * C;

    const int smem = (C * C + 2 * C + 2 * (2 * C) + 16) * sizeof(float);
    cudaFuncSetAttribute(softmax_sigma_kernel,
                         cudaFuncAttributeMaxDynamicSharedMemorySize, smem);
    softmax_sigma_kernel<<<B, THREADS, smem>>>(mu, Sigma, mu_out, sig_out);
}